// round 1
// baseline (speedup 1.0000x reference)
#include <cuda_runtime.h>

// IF spiking neuron forward: T=8 scan, soft reset, spike = thresh * (mem >= thresh).
// x: [T*B, C, H, W] f32, thresh: [1] f32, out: same shape as x.
// Per-neuron (b,c,h,w): mem = 0.5*thr; for t: m = mem + x[t]; sp = (m>=thr)?thr:0;
//                       out[t] = sp; mem = m - sp.
// Timestep stride in elements = B*C*H*W = 4,194,304. T = 8.

#ifndef IF_T
#define IF_T 8
#endif

__global__ __launch_bounds__(256, 8)
void if_scan_kernel(const float4* __restrict__ x,
                    const float* __restrict__ thresh,
                    float4* __restrict__ out,
                    int n_vec, int stride_vec)
{
    int n = blockIdx.x * blockDim.x + threadIdx.x;
    if (n >= n_vec) return;

    const float thr = thresh[0];

    // Front-batch all T independent loads (MLP = 8, 128B/thread in flight)
    float4 xt[IF_T];
#pragma unroll
    for (int t = 0; t < IF_T; ++t)
        xt[t] = x[(size_t)t * stride_vec + n];

    float4 mem;
    mem.x = 0.5f * thr; mem.y = 0.5f * thr; mem.z = 0.5f * thr; mem.w = 0.5f * thr;

    float4 sp[IF_T];
#pragma unroll
    for (int t = 0; t < IF_T; ++t) {
        float mx = mem.x + xt[t].x;
        float my = mem.y + xt[t].y;
        float mz = mem.z + xt[t].z;
        float mw = mem.w + xt[t].w;
        float sx = (mx >= thr) ? thr : 0.0f;
        float sy = (my >= thr) ? thr : 0.0f;
        float sz = (mz >= thr) ? thr : 0.0f;
        float sw = (mw >= thr) ? thr : 0.0f;
        sp[t].x = sx; sp[t].y = sy; sp[t].z = sz; sp[t].w = sw;
        mem.x = mx - sx; mem.y = my - sy; mem.z = mz - sz; mem.w = mw - sw;
    }

#pragma unroll
    for (int t = 0; t < IF_T; ++t)
        out[(size_t)t * stride_vec + n] = sp[t];
}

extern "C" void kernel_launch(void* const* d_in, const int* in_sizes, int n_in,
                              void* d_out, int out_size)
{
    const float* x      = (const float*)d_in[0];
    const float* thresh = (const float*)d_in[1];
    float* out          = (float*)d_out;

    const int total = in_sizes[0];          // T*B*C*H*W = 33,554,432
    const int stride = total / IF_T;        // per-timestep elements = 4,194,304
    const int stride_vec = stride / 4;      // float4 units = 1,048,576
    const int n_vec = stride_vec;           // one thread per 4 neurons

    const int threads = 256;
    const int blocks = (n_vec + threads - 1) / threads;

    if_scan_kernel<<<blocks, threads>>>((const float4*)x, thresh,
                                        (float4*)out, n_vec, stride_vec);
}